// round 10
// baseline (speedup 1.0000x reference)
#include <cuda_runtime.h>
#include <cuda_fp16.h>
#include <math.h>
#include <stdint.h>

// ---- problem constants ----
#define OC     128
#define IC     64
#define SPAN   576
#define TSIZE  8
#define MLSH   5
#define HH     56
#define WW     56
#define BATCH  16
#define IMG    (HH*WW)      // 3136
#define NPIX   (BATCH*IMG)  // 50176
#define NCHUNK 9            // permuted k: chunk == filter tap (dy,dx)

// ---- device scratch ----
__device__ int   g_counts[TSIZE];
__device__ float g_factor[OC];
// A operands (fp16 hi only), mma-fragment order, PERMUTED k (k' = rr*64 + c):
// [ch][wm][mt][ks][lane] -> uint4
__device__ __align__(16) uint4 g_Wfrag[NCHUNK * 2 * 4 * 4 * 32];   // 144 KB
// x split packed fp16: hi | lo<<16 per element, layout [b][c][y][x]
__device__ __align__(16) uint32_t g_xs[BATCH * IC * IMG];

// ============================================================
// helpers
// ============================================================
__device__ __forceinline__ uint32_t smem_u32(const void* p) {
    uint32_t a;
    asm("{ .reg .u64 t; cvta.to.shared.u64 t, %1; cvt.u32.u64 %0, t; }" : "=r"(a) : "l"(p));
    return a;
}
__device__ __forceinline__ uint32_t swz(uint32_t off) { return off ^ ((off >> 3) & 0x70); }

__device__ __forceinline__ void ldsm_x4(uint32_t* r, uint32_t addr) {
    asm volatile("ldmatrix.sync.aligned.m8n8.x4.shared.b16 {%0,%1,%2,%3}, [%4];"
        : "=r"(r[0]), "=r"(r[1]), "=r"(r[2]), "=r"(r[3]) : "r"(addr));
}
// HMMA m16n8k16 fp16 -> fp32
__device__ __forceinline__ void mma_f16(float* c, const uint32_t* a, const uint32_t* b) {
    asm volatile(
        "mma.sync.aligned.m16n8k16.row.col.f32.f16.f16.f32 "
        "{%0,%1,%2,%3}, {%4,%5,%6,%7}, {%8,%9}, {%0,%1,%2,%3};"
        : "+f"(c[0]), "+f"(c[1]), "+f"(c[2]), "+f"(c[3])
        : "r"(a[0]), "r"(a[1]), "r"(a[2]), "r"(a[3]), "r"(b[0]), "r"(b[1]));
}

__device__ __forceinline__ int bucket_of(float h, float b) {
    float q = floorf((h + b) / 2.5f);
    int i = (int)q;
    int r = i % TSIZE;
    return r < 0 ? -r : r;
}

// fp16 split: hi = rn(v), lo = rn(v - hi); packed hi | lo<<16
__device__ __forceinline__ uint32_t split_pack(float v) {
    __half h = __float2half_rn(v);
    __half l = __float2half_rn(v - __half2float(h));
    return (uint32_t)__half_as_ushort(h) | ((uint32_t)__half_as_ushort(l) << 16);
}
__device__ __forceinline__ uint32_t pack2h(float a, float b) {   // fp16 hi pair
    return (uint32_t)__half_as_ushort(__float2half_rn(a))
         | ((uint32_t)__half_as_ushort(__float2half_rn(b)) << 16);
}

__global__ void init_counts_kernel() {
    if (threadIdx.x < TSIZE) g_counts[threadIdx.x] = 0;
}

// ------------------------------------------------------------------
// prep_w: fp16-hi fragments with PERMUTED k (pos -> W[..][pos*9 + ch])
// ------------------------------------------------------------------
__global__ __launch_bounds__(256) void prep_w_kernel(const float* __restrict__ W) {
    int i = blockIdx.x * 256 + threadIdx.x;     // 9216 = 36 * 256
    int lane = i & 31;
    int ks   = (i >> 5) & 3;
    int mt   = (i >> 7) & 3;
    int wm   = (i >> 9) & 1;
    int ch   = i >> 10;                          // 0..8 (tap)

    int r   = wm * 64 + mt * 16 + (lane >> 2);
    int pos = ks * 16 + (lane & 3) * 2;

    const float* Wr  = W + (size_t)r * SPAN + ch;
    const float* Wr8 = Wr + 8 * SPAN;

    uint4 hi = make_uint4(
        pack2h(Wr[pos * 9],        Wr[(pos + 1) * 9]),
        pack2h(Wr8[pos * 9],       Wr8[(pos + 1) * 9]),
        pack2h(Wr[(pos + 8) * 9],  Wr[(pos + 9) * 9]),
        pack2h(Wr8[(pos + 8) * 9], Wr8[(pos + 9) * 9]));

    g_Wfrag[(((ch * 2 + wm) * 4 + mt) * 4 + ks) * 32 + lane] = hi;
}

// ------------------------------------------------------------------
// prep_x: split x into packed fp16 (hi | lo<<16)
// ------------------------------------------------------------------
__global__ __launch_bounds__(256) void prep_x_kernel(const float* __restrict__ x) {
    int i = blockIdx.x * 256 + threadIdx.x;
    float4 v = ((const float4*)x)[i];
    uint4 o;
    o.x = split_pack(v.x); o.y = split_pack(v.y);
    o.z = split_pack(v.z); o.w = split_pack(v.w);
    ((uint4*)g_xs)[i] = o;
}

// ------------------------------------------------------------------
// Vote pass (unchanged)
// ------------------------------------------------------------------
__global__ __launch_bounds__(256) void vote_kernel(
    const float* __restrict__ x, const float* __restrict__ a, const float* __restrict__ bptr)
{
    __shared__ float sx[IC * 3 * WW];
    __shared__ float sa[SPAN + MLSH];
    __shared__ float partial[WW][4];
    __shared__ int hist[TSIZE];

    const int tid = threadIdx.x;
    const int b   = blockIdx.x / HH;
    const int y   = blockIdx.x % HH;

    for (int i = tid; i < SPAN + MLSH; i += 256) sa[i] = a[i];
    if (tid < TSIZE) hist[tid] = 0;

    const float* xb = x + (size_t)b * IC * IMG;
    for (int idx = tid; idx < IC * 3 * WW; idx += 256) {
        int c   = idx / (3 * WW);
        int rem = idx - c * (3 * WW);
        int r   = rem / WW;
        int xx  = rem - r * WW;
        int yy  = y + r - 1;
        sx[idx] = ((unsigned)yy < HH) ? xb[c * IMG + yy * WW + xx] : 0.0f;
    }
    __syncthreads();

    const int g  = tid >> 6;
    const int xx = tid & 63;
    if (xx < WW) {
        float v = 0.0f;
        #pragma unroll 4
        for (int ci = 0; ci < 16; ci++) {
            int c = g * 16 + ci;
            const float* sxc = sx + c * (3 * WW);
            const float* sac = sa + c * 9;
            #pragma unroll
            for (int r = 0; r < 3; r++)
                #pragma unroll
                for (int dx = 0; dx < 3; dx++) {
                    int xq = xx + dx - 1;
                    if ((unsigned)xq < WW) v += sac[r * 3 + dx] * sxc[r * WW + xq];
                }
        }
        partial[xx][g] = v;
    }
    __syncthreads();

    if (tid < WW) {
        float v = partial[tid][0] + partial[tid][1] + partial[tid][2] + partial[tid][3];
        float q = 0.0f;
        #pragma unroll
        for (int i = 0; i < MLSH; i++) q += sa[SPAN + i];
        v += 0.5f * q;
        atomicAdd(&hist[bucket_of(v, bptr[0])], 1);
    }
    __syncthreads();
    if (tid < TSIZE) atomicAdd(&g_counts[tid], hist[tid]);
}

// ------------------------------------------------------------------
// Factor pass (unchanged)
// ------------------------------------------------------------------
__global__ __launch_bounds__(128) void factor_kernel(
    const float* __restrict__ kernels, const float* __restrict__ a, const float* __restrict__ bptr)
{
    __shared__ float sa[SPAN + MLSH];
    __shared__ int sh_bucket, sh_cnt;
    for (int i = threadIdx.x; i < SPAN + MLSH; i += blockDim.x) sa[i] = a[i];
    if (threadIdx.x == 0) {
        int best = 0, bi = 0;
        #pragma unroll
        for (int t = 0; t < TSIZE; t++) { int c = g_counts[t]; if (c > best) { best = c; bi = t; } }
        sh_bucket = bi; sh_cnt = 0;
    }
    __syncthreads();

    int oc = threadIdx.x;
    const float* w = kernels + (size_t)oc * SPAN;
    float dot = 0.0f, nrm = 0.0f;
    for (int k = 0; k < SPAN; k++) { float wv = w[k]; dot += wv * sa[k]; nrm += wv * wv; }
    float s = nrm, paug = 0.0f;
    #pragma unroll
    for (int i = 0; i < MLSH; i++) { paug += s * sa[SPAN + i]; s = s * s; }
    int kidx = bucket_of(dot + paug, bptr[0]);
    int in_bucket = (kidx == sh_bucket) ? 1 : 0;
    atomicAdd(&sh_cnt, in_bucket);
    __syncthreads();
    int cnt = sh_cnt;
    g_factor[oc] = (cnt > 0) ? (in_bucket ? ((float)OC / (float)cnt) : 0.0f) : 1.0f;
}

// ------------------------------------------------------------------
// HMMA conv GEMM, fp16 2-pass:  out = Whi*(Xhi + Xlo)
//   chunk == filter tap; B gather: one bounds test/chunk, stride-IMG.
//   A: LDG.128 hi fragments from g_Wfrag. B double-buffered smem.
// ------------------------------------------------------------------
#define STAGE     32768     // B_HI(16K) + B_LO(16K)
#define DYN_SMEM  (2*STAGE + 1024)

__device__ __forceinline__ void gather16p(const uint32_t* __restrict__ base,
                                          bool valid, uint32_t* u) {
    #pragma unroll
    for (int j = 0; j < 16; j++)
        u[j] = valid ? base[j * IMG] : 0u;
}
__device__ __forceinline__ void sts16(char* stage, uint32_t row_off, int kb16,
                                      const uint32_t* u) {
    #pragma unroll
    for (int p = 0; p < 2; p++) {
        uint32_t hw[4], lw[4];
        #pragma unroll
        for (int e = 0; e < 4; e++) {
            uint32_t u0 = u[p * 8 + e * 2], u1 = u[p * 8 + e * 2 + 1];
            hw[e] = (u0 & 0xffffu) | (u1 << 16);
            lw[e] = (u0 >> 16) | (u1 & 0xffff0000u);
        }
        uint32_t addr = swz(row_off + (uint32_t)(kb16 + p * 8) * 2);
        *(uint4*)(stage +         addr) = make_uint4(hw[0], hw[1], hw[2], hw[3]);
        *(uint4*)(stage + 16384 + addr) = make_uint4(lw[0], lw[1], lw[2], lw[3]);
    }
}

// one k-step (k16): A LDG (hi only) + B ldsm + 32 MMAs (2 passes)
__device__ __forceinline__ void mma_ks(uint32_t buf_u, const uint4* __restrict__ Af,
                                       int ks, uint32_t b_row, float (*acc)[4][4]) {
    const uint32_t kb = (uint32_t)ks * 32;
    uint4 af[4];
    #pragma unroll
    for (int mt = 0; mt < 4; mt++)
        af[mt] = Af[(mt * 4 + ks) * 32];

    uint32_t bhf[4][2], blf[4][2];
    #pragma unroll
    for (int p = 0; p < 2; p++) {
        uint32_t t[4];
        ldsm_x4(t, buf_u + swz(b_row + (uint32_t)p * 2048 + kb));
        bhf[p*2+0][0] = t[0]; bhf[p*2+0][1] = t[1];
        bhf[p*2+1][0] = t[2]; bhf[p*2+1][1] = t[3];
    }
    #pragma unroll
    for (int p = 0; p < 2; p++) {
        uint32_t t[4];
        ldsm_x4(t, buf_u + 16384 + swz(b_row + (uint32_t)p * 2048 + kb));
        blf[p*2+0][0] = t[0]; blf[p*2+0][1] = t[1];
        blf[p*2+1][0] = t[2]; blf[p*2+1][1] = t[3];
    }

    #pragma unroll
    for (int mt = 0; mt < 4; mt++)
        #pragma unroll
        for (int nt = 0; nt < 4; nt++) {
            mma_f16(acc[mt][nt], (const uint32_t*)&af[mt], bhf[nt]);
            mma_f16(acc[mt][nt], (const uint32_t*)&af[mt], blf[nt]);
        }
}

__global__ __launch_bounds__(256, 2)
void conv_hmma_kernel(float* __restrict__ out)
{
    extern __shared__ char dsm[];
    char* sb = (char*)(((uintptr_t)dsm + 1023) & ~(uintptr_t)1023);
    const uint32_t sb_u = smem_u32(sb);

    const int tid  = threadIdx.x;
    const int wid  = tid >> 5;
    const int lane = tid & 31;
    const int n0   = blockIdx.x * 128;

    const int wm = wid >> 2;
    const int wn = wid & 3;

    // ---- B staging geometry: 2 threads per pixel row, 32 channels each ----
    const int rown  = tid >> 1;
    const int kbase = (tid & 1) * 32;
    const int n     = n0 + rown;
    const int bimg  = n / IMG;
    const int pix   = n - bimg * IMG;
    const int y0    = pix / WW;
    const int x0    = pix - y0 * WW;
    const uint32_t* xk = g_xs + (size_t)bimg * IC * IMG + kbase * IMG;
    const uint32_t row_off = (uint32_t)rown * 128;

    const uint32_t b_row = (uint32_t)(wn * 32 + (lane & 7) + ((lane >> 4) << 3)) * 128
                         + (((lane >> 3) & 1) << 4);

    float acc[4][4][4];
    #pragma unroll
    for (int i = 0; i < 4; i++)
        #pragma unroll
        for (int j = 0; j < 4; j++)
            #pragma unroll
            for (int q = 0; q < 4; q++) acc[i][j][q] = 0.0f;

    // ---- prologue: stage chunk 0 (tap dy=0,dx=0) ----
    {
        const int yy = y0 - 1, xx = x0 - 1;
        const bool valid = ((unsigned)yy < HH) && ((unsigned)xx < WW);
        const uint32_t* basep = xk + yy * WW + xx;
        uint32_t u[16];
        gather16p(basep, valid, u);
        sts16(sb, row_off, kbase, u);
        gather16p(basep + 16 * IMG, valid, u);
        sts16(sb, row_off, kbase + 16, u);
    }
    __syncthreads();

    // ---- main loop: one sync per chunk ----
    for (int ch = 0; ch < NCHUNK; ch++) {
        const uint32_t cur_u = sb_u + (uint32_t)(ch & 1) * STAGE;
        char* nxt = sb + ((ch + 1) & 1) * STAGE;
        const uint4* Af = g_Wfrag + ch * 1024 + wm * 512 + lane;
        const bool more = (ch + 1 < NCHUNK);

        const int chn = ch + 1;
        const int dyn = chn / 3, dxn = chn - dyn * 3;
        const int yy  = y0 + dyn - 1, xx = x0 + dxn - 1;
        const bool valid = more && ((unsigned)yy < HH) && ((unsigned)xx < WW);
        const uint32_t* basep = xk + yy * WW + xx;

        uint32_t u[16];
        if (more) gather16p(basep, valid, u);        // LDGs overlap MMA

        mma_ks(cur_u, Af, 0, b_row, acc);
        mma_ks(cur_u, Af, 1, b_row, acc);

        if (more) {
            sts16(nxt, row_off, kbase, u);
            gather16p(basep + 16 * IMG, valid, u);
        }

        mma_ks(cur_u, Af, 2, b_row, acc);
        mma_ks(cur_u, Af, 3, b_row, acc);

        if (more) sts16(nxt, row_off, kbase + 16, u);
        __syncthreads();
    }

    // ---- epilogue: apply factor, store ----
    #pragma unroll
    for (int mt = 0; mt < 4; mt++) {
        const int m0 = wm * 64 + mt * 16 + (lane >> 2);
        const float f0 = g_factor[m0];
        const float f1 = g_factor[m0 + 8];
        #pragma unroll
        for (int nt = 0; nt < 4; nt++) {
            const int np = n0 + wn * 32 + nt * 8 + (lane & 3) * 2;
            const int bb = np / IMG;
            const int pp = np - bb * IMG;
            float* o0 = out + ((size_t)bb * OC + m0) * IMG + pp;
            *(float2*)o0             = make_float2(acc[mt][nt][0] * f0, acc[mt][nt][1] * f0);
            *(float2*)(o0 + 8 * IMG) = make_float2(acc[mt][nt][2] * f1, acc[mt][nt][3] * f1);
        }
    }
}

// ------------------------------------------------------------------
extern "C" void kernel_launch(void* const* d_in, const int* in_sizes, int n_in,
                              void* d_out, int out_size)
{
    const float* x       = (const float*)d_in[0];
    const float* kernels = (const float*)d_in[1];
    const float* a       = (const float*)d_in[2];
    const float* b       = (const float*)d_in[3];
    float* out = (float*)d_out;

    static bool attr_set = false;
    if (!attr_set) {
        cudaFuncSetAttribute(conv_hmma_kernel,
                             cudaFuncAttributeMaxDynamicSharedMemorySize, DYN_SMEM);
        attr_set = true;
    }

    init_counts_kernel<<<1, 32>>>();
    prep_w_kernel<<<36, 256>>>(kernels);
    prep_x_kernel<<<(BATCH * IC * IMG) / 4 / 256, 256>>>(x);
    vote_kernel<<<BATCH * HH, 256>>>(x, a, b);
    factor_kernel<<<1, 128>>>(kernels, a, b);
    conv_hmma_kernel<<<NPIX / 128, 256, DYN_SMEM>>>(out);
}

// round 11
// speedup vs baseline: 1.5430x; 1.5430x over previous
#include <cuda_runtime.h>
#include <cuda_fp16.h>
#include <math.h>
#include <stdint.h>

// ---- problem constants ----
#define OC     128
#define IC     64
#define SPAN   576
#define TSIZE  8
#define MLSH   5
#define HH     56
#define WW     56
#define BATCH  16
#define IMG    (HH*WW)      // 3136
#define NPIX   (BATCH*IMG)  // 50176
#define NCHUNK 9            // permuted k: chunk == filter tap (dy,dx)

// ---- device scratch ----
__device__ int   g_counts[TSIZE];
__device__ float g_factor[OC];
// A operands (fp16 hi), mma-fragment order, PERMUTED k (k' = rr*64 + c):
// [ch][wm][mt][ks][lane] -> uint4
__device__ __align__(16) uint4 g_Wfrag[NCHUNK * 2 * 4 * 4 * 32];   // 144 KB
// x split packed fp16: hi | lo<<16, layout [b][c][y][x]
__device__ __align__(16) uint32_t g_xs[BATCH * IC * IMG];

// ============================================================
// helpers
// ============================================================
__device__ __forceinline__ uint32_t smem_u32(const void* p) {
    uint32_t a;
    asm("{ .reg .u64 t; cvta.to.shared.u64 t, %1; cvt.u32.u64 %0, t; }" : "=r"(a) : "l"(p));
    return a;
}
__device__ __forceinline__ uint32_t swz(uint32_t off) { return off ^ ((off >> 3) & 0x70); }

__device__ __forceinline__ void ldsm_x4(uint32_t* r, uint32_t addr) {
    asm volatile("ldmatrix.sync.aligned.m8n8.x4.shared.b16 {%0,%1,%2,%3}, [%4];"
        : "=r"(r[0]), "=r"(r[1]), "=r"(r[2]), "=r"(r[3]) : "r"(addr));
}
__device__ __forceinline__ void mma_f16(float* c, const uint32_t* a, const uint32_t* b) {
    asm volatile(
        "mma.sync.aligned.m16n8k16.row.col.f32.f16.f16.f32 "
        "{%0,%1,%2,%3}, {%4,%5,%6,%7}, {%8,%9}, {%0,%1,%2,%3};"
        : "+f"(c[0]), "+f"(c[1]), "+f"(c[2]), "+f"(c[3])
        : "r"(a[0]), "r"(a[1]), "r"(a[2]), "r"(a[3]), "r"(b[0]), "r"(b[1]));
}

__device__ __forceinline__ int bucket_of(float h, float b) {
    float q = floorf((h + b) / 2.5f);
    int i = (int)q;
    int r = i % TSIZE;
    return r < 0 ? -r : r;
}

__device__ __forceinline__ uint32_t split_pack(float v) {
    __half h = __float2half_rn(v);
    __half l = __float2half_rn(v - __half2float(h));
    return (uint32_t)__half_as_ushort(h) | ((uint32_t)__half_as_ushort(l) << 16);
}
__device__ __forceinline__ uint32_t pack2h(float a, float b) {
    return (uint32_t)__half_as_ushort(__float2half_rn(a))
         | ((uint32_t)__half_as_ushort(__float2half_rn(b)) << 16);
}

__global__ void init_counts_kernel() {
    if (threadIdx.x < TSIZE) g_counts[threadIdx.x] = 0;
}

// ------------------------------------------------------------------
// prep_w: fp16-hi fragments with PERMUTED k (pos -> W[..][pos*9 + ch])
// ------------------------------------------------------------------
__global__ __launch_bounds__(256) void prep_w_kernel(const float* __restrict__ W) {
    int i = blockIdx.x * 256 + threadIdx.x;     // 9216 = 36 * 256
    int lane = i & 31;
    int ks   = (i >> 5) & 3;
    int mt   = (i >> 7) & 3;
    int wm   = (i >> 9) & 1;
    int ch   = i >> 10;

    int r   = wm * 64 + mt * 16 + (lane >> 2);
    int pos = ks * 16 + (lane & 3) * 2;

    const float* Wr  = W + (size_t)r * SPAN + ch;
    const float* Wr8 = Wr + 8 * SPAN;

    uint4 hi = make_uint4(
        pack2h(Wr[pos * 9],        Wr[(pos + 1) * 9]),
        pack2h(Wr8[pos * 9],       Wr8[(pos + 1) * 9]),
        pack2h(Wr[(pos + 8) * 9],  Wr[(pos + 9) * 9]),
        pack2h(Wr8[(pos + 8) * 9], Wr8[(pos + 9) * 9]));

    g_Wfrag[(((ch * 2 + wm) * 4 + mt) * 4 + ks) * 32 + lane] = hi;
}

// ------------------------------------------------------------------
// prep_x: split x into packed fp16 (hi | lo<<16)
// ------------------------------------------------------------------
__global__ __launch_bounds__(256) void prep_x_kernel(const float* __restrict__ x) {
    int i = blockIdx.x * 256 + threadIdx.x;
    float4 v = ((const float4*)x)[i];
    uint4 o;
    o.x = split_pack(v.x); o.y = split_pack(v.y);
    o.z = split_pack(v.z); o.w = split_pack(v.w);
    ((uint4*)g_xs)[i] = o;
}

// ------------------------------------------------------------------
// Vote pass: padded smem rows (58 cols, zero borders) -> branch-free
// 144-FMA inner loop per (channel-group, pixel).
// ------------------------------------------------------------------
#define PW 58                      // padded width
__global__ __launch_bounds__(256) void vote_kernel(
    const float* __restrict__ x, const float* __restrict__ a, const float* __restrict__ bptr)
{
    __shared__ float sx[IC * 3 * PW];      // 44544 B, zero-padded borders
    __shared__ float sa[SPAN + MLSH];
    __shared__ float partial[WW][4];
    __shared__ int hist[TSIZE];

    const int tid = threadIdx.x;
    const int b   = blockIdx.x / HH;
    const int y   = blockIdx.x % HH;

    for (int i = tid; i < SPAN + MLSH; i += 256) sa[i] = a[i];
    if (tid < TSIZE) hist[tid] = 0;

    const float* xb = x + (size_t)b * IC * IMG;
    for (int idx = tid; idx < IC * 3 * PW; idx += 256) {
        int c   = idx / (3 * PW);
        int rem = idx - c * (3 * PW);
        int r   = rem / PW;
        int px  = rem - r * PW;          // 0..57 ; real x = px-1
        int yy  = y + r - 1;
        float v = 0.0f;
        if (px >= 1 && px <= WW && (unsigned)yy < HH)
            v = xb[c * IMG + yy * WW + (px - 1)];
        sx[idx] = v;
    }
    __syncthreads();

    const int g  = tid >> 6;       // channel group 0..3
    const int xx = tid & 63;       // pixel (>=56 idle)
    if (xx < WW) {
        float v = 0.0f;
        const float* base0 = sx + (g * 16) * (3 * PW) + xx;
        const float* sac0  = sa + (g * 16) * 9;
        #pragma unroll 4
        for (int ci = 0; ci < 16; ci++) {
            const float* basec = base0 + ci * (3 * PW);
            const float* sac   = sac0 + ci * 9;
            #pragma unroll
            for (int r = 0; r < 3; r++)
                #pragma unroll
                for (int dx = 0; dx < 3; dx++)
                    v += sac[r * 3 + dx] * basec[r * PW + dx];
        }
        partial[xx][g] = v;
    }
    __syncthreads();

    if (tid < WW) {
        float v = partial[tid][0] + partial[tid][1] + partial[tid][2] + partial[tid][3];
        float q = 0.0f;
        #pragma unroll
        for (int i = 0; i < MLSH; i++) q += sa[SPAN + i];
        v += 0.5f * q;
        atomicAdd(&hist[bucket_of(v, bptr[0])], 1);
    }
    __syncthreads();
    if (tid < TSIZE) atomicAdd(&g_counts[tid], hist[tid]);
}

// ------------------------------------------------------------------
// Factor pass
// ------------------------------------------------------------------
__global__ __launch_bounds__(128) void factor_kernel(
    const float* __restrict__ kernels, const float* __restrict__ a, const float* __restrict__ bptr)
{
    __shared__ float sa[SPAN + MLSH];
    __shared__ int sh_bucket, sh_cnt;
    for (int i = threadIdx.x; i < SPAN + MLSH; i += blockDim.x) sa[i] = a[i];
    if (threadIdx.x == 0) {
        int best = 0, bi = 0;
        #pragma unroll
        for (int t = 0; t < TSIZE; t++) { int c = g_counts[t]; if (c > best) { best = c; bi = t; } }
        sh_bucket = bi; sh_cnt = 0;
    }
    __syncthreads();

    int oc = threadIdx.x;
    const float* w = kernels + (size_t)oc * SPAN;
    float dot = 0.0f, nrm = 0.0f;
    for (int k = 0; k < SPAN; k++) { float wv = w[k]; dot += wv * sa[k]; nrm += wv * wv; }
    float s = nrm, paug = 0.0f;
    #pragma unroll
    for (int i = 0; i < MLSH; i++) { paug += s * sa[SPAN + i]; s = s * s; }
    int kidx = bucket_of(dot + paug, bptr[0]);
    int in_bucket = (kidx == sh_bucket) ? 1 : 0;
    atomicAdd(&sh_cnt, in_bucket);
    __syncthreads();
    int cnt = sh_cnt;
    g_factor[oc] = (cnt > 0) ? (in_bucket ? ((float)OC / (float)cnt) : 0.0f) : 1.0f;
}

// ------------------------------------------------------------------
// HMMA conv GEMM, fp16 2-pass: out = Whi*(Xhi + Xlo)
// ------------------------------------------------------------------
#define STAGE     32768     // B_HI(16K) + B_LO(16K)
#define DYN_SMEM  (2*STAGE + 1024)

__device__ __forceinline__ void gather16p(const uint32_t* __restrict__ base,
                                          bool valid, uint32_t* u) {
    #pragma unroll
    for (int j = 0; j < 16; j++)
        u[j] = valid ? base[j * IMG] : 0u;
}
__device__ __forceinline__ void sts16(char* stage, uint32_t row_off, int kb16,
                                      const uint32_t* u) {
    #pragma unroll
    for (int p = 0; p < 2; p++) {
        uint32_t hw[4], lw[4];
        #pragma unroll
        for (int e = 0; e < 4; e++) {
            uint32_t u0 = u[p * 8 + e * 2], u1 = u[p * 8 + e * 2 + 1];
            hw[e] = (u0 & 0xffffu) | (u1 << 16);
            lw[e] = (u0 >> 16) | (u1 & 0xffff0000u);
        }
        uint32_t addr = swz(row_off + (uint32_t)(kb16 + p * 8) * 2);
        *(uint4*)(stage +         addr) = make_uint4(hw[0], hw[1], hw[2], hw[3]);
        *(uint4*)(stage + 16384 + addr) = make_uint4(lw[0], lw[1], lw[2], lw[3]);
    }
}

__device__ __forceinline__ void mma_ks(uint32_t buf_u, const uint4* __restrict__ Af,
                                       int ks, uint32_t b_row, float (*acc)[4][4]) {
    const uint32_t kb = (uint32_t)ks * 32;
    uint4 af[4];
    #pragma unroll
    for (int mt = 0; mt < 4; mt++)
        af[mt] = Af[(mt * 4 + ks) * 32];

    uint32_t bhf[4][2], blf[4][2];
    #pragma unroll
    for (int p = 0; p < 2; p++) {
        uint32_t t[4];
        ldsm_x4(t, buf_u + swz(b_row + (uint32_t)p * 2048 + kb));
        bhf[p*2+0][0] = t[0]; bhf[p*2+0][1] = t[1];
        bhf[p*2+1][0] = t[2]; bhf[p*2+1][1] = t[3];
    }
    #pragma unroll
    for (int p = 0; p < 2; p++) {
        uint32_t t[4];
        ldsm_x4(t, buf_u + 16384 + swz(b_row + (uint32_t)p * 2048 + kb));
        blf[p*2+0][0] = t[0]; blf[p*2+0][1] = t[1];
        blf[p*2+1][0] = t[2]; blf[p*2+1][1] = t[3];
    }

    #pragma unroll
    for (int mt = 0; mt < 4; mt++)
        #pragma unroll
        for (int nt = 0; nt < 4; nt++) {
            mma_f16(acc[mt][nt], (const uint32_t*)&af[mt], bhf[nt]);
            mma_f16(acc[mt][nt], (const uint32_t*)&af[mt], blf[nt]);
        }
}

__global__ __launch_bounds__(256, 2)
void conv_hmma_kernel(float* __restrict__ out)
{
    extern __shared__ char dsm[];
    char* sb = (char*)(((uintptr_t)dsm + 1023) & ~(uintptr_t)1023);
    const uint32_t sb_u = smem_u32(sb);

    const int tid  = threadIdx.x;
    const int wid  = tid >> 5;
    const int lane = tid & 31;
    const int n0   = blockIdx.x * 128;

    const int wm = wid >> 2;
    const int wn = wid & 3;

    const int rown  = tid >> 1;
    const int kbase = (tid & 1) * 32;
    const int n     = n0 + rown;
    const int bimg  = n / IMG;
    const int pix   = n - bimg * IMG;
    const int y0    = pix / WW;
    const int x0    = pix - y0 * WW;
    const uint32_t* xk = g_xs + (size_t)bimg * IC * IMG + kbase * IMG;
    const uint32_t row_off = (uint32_t)rown * 128;

    const uint32_t b_row = (uint32_t)(wn * 32 + (lane & 7) + ((lane >> 4) << 3)) * 128
                         + (((lane >> 3) & 1) << 4);

    float acc[4][4][4];
    #pragma unroll
    for (int i = 0; i < 4; i++)
        #pragma unroll
        for (int j = 0; j < 4; j++)
            #pragma unroll
            for (int q = 0; q < 4; q++) acc[i][j][q] = 0.0f;

    // ---- prologue: stage chunk 0 (tap dy=0,dx=0) ----
    {
        const int yy = y0 - 1, xx = x0 - 1;
        const bool valid = ((unsigned)yy < HH) && ((unsigned)xx < WW);
        const uint32_t* basep = xk + yy * WW + xx;
        uint32_t u[16];
        gather16p(basep, valid, u);
        sts16(sb, row_off, kbase, u);
        gather16p(basep + 16 * IMG, valid, u);
        sts16(sb, row_off, kbase + 16, u);
    }
    __syncthreads();

    for (int ch = 0; ch < NCHUNK; ch++) {
        const uint32_t cur_u = sb_u + (uint32_t)(ch & 1) * STAGE;
        char* nxt = sb + ((ch + 1) & 1) * STAGE;
        const uint4* Af = g_Wfrag + ch * 1024 + wm * 512 + lane;
        const bool more = (ch + 1 < NCHUNK);

        const int chn = ch + 1;
        const int dyn = chn / 3, dxn = chn - dyn * 3;
        const int yy  = y0 + dyn - 1, xx = x0 + dxn - 1;
        const bool valid = more && ((unsigned)yy < HH) && ((unsigned)xx < WW);
        const uint32_t* basep = xk + yy * WW + xx;

        uint32_t u[16];
        if (more) gather16p(basep, valid, u);

        mma_ks(cur_u, Af, 0, b_row, acc);
        mma_ks(cur_u, Af, 1, b_row, acc);

        if (more) {
            sts16(nxt, row_off, kbase, u);
            gather16p(basep + 16 * IMG, valid, u);
        }

        mma_ks(cur_u, Af, 2, b_row, acc);
        mma_ks(cur_u, Af, 3, b_row, acc);

        if (more) sts16(nxt, row_off, kbase + 16, u);
        __syncthreads();
    }

    // ---- epilogue: apply factor, store ----
    #pragma unroll
    for (int mt = 0; mt < 4; mt++) {
        const int m0 = wm * 64 + mt * 16 + (lane >> 2);
        const float f0 = g_factor[m0];
        const float f1 = g_factor[m0 + 8];
        #pragma unroll
        for (int nt = 0; nt < 4; nt++) {
            const int np = n0 + wn * 32 + nt * 8 + (lane & 3) * 2;
            const int bb = np / IMG;
            const int pp = np - bb * IMG;
            float* o0 = out + ((size_t)bb * OC + m0) * IMG + pp;
            *(float2*)o0             = make_float2(acc[mt][nt][0] * f0, acc[mt][nt][1] * f0);
            *(float2*)(o0 + 8 * IMG) = make_float2(acc[mt][nt][2] * f1, acc[mt][nt][3] * f1);
        }
    }
}

// ------------------------------------------------------------------
extern "C" void kernel_launch(void* const* d_in, const int* in_sizes, int n_in,
                              void* d_out, int out_size)
{
    const float* x       = (const float*)d_in[0];
    const float* kernels = (const float*)d_in[1];
    const float* a       = (const float*)d_in[2];
    const float* b       = (const float*)d_in[3];
    float* out = (float*)d_out;

    static bool attr_set = false;
    if (!attr_set) {
        cudaFuncSetAttribute(conv_hmma_kernel,
                             cudaFuncAttributeMaxDynamicSharedMemorySize, DYN_SMEM);
        attr_set = true;
    }

    init_counts_kernel<<<1, 32>>>();
    prep_w_kernel<<<36, 256>>>(kernels);
    prep_x_kernel<<<(BATCH * IC * IMG) / 4 / 256, 256>>>(x);
    vote_kernel<<<BATCH * HH, 256>>>(x, a, b);
    factor_kernel<<<1, 128>>>(kernels, a, b);
    conv_hmma_kernel<<<NPIX / 128, 256, DYN_SMEM>>>(out);
}